// round 8
// baseline (speedup 1.0000x reference)
#include <cuda_runtime.h>

// Blur: depthwise 4x4 FIR (separable [1,3,3,1] ⊗ [1,3,3,1] / 16), pad (1,1).
// Input (4,128,513,513) f32 -> Output (4,128,512,512) f32.
//
// Round-8: R7 fence-free shuffle body (no smem, no syncwarp; halo via
// shfl_up/down + 1 predicated edge load) with occupancy raised to 10 CTAs/SM
// (48-reg cap -> 62.5% occ cap, better wave packing: 4096/1480 = 2.77 waves)
// and evict-first streaming stores (__stcs) for the never-re-read output.

#define W_IN   513
#define H_IN   513
#define W_OUT  512
#define H_OUT  512
#define STRIP  64
#define NPLANE 512      // 4*128
#define FULL   0xffffffffu

__global__ __launch_bounds__(128, 10)
void blur_shfl10_kernel(const float* __restrict__ in, float* __restrict__ out)
{
    const int tid   = threadIdx.x;
    const int warp  = tid >> 5;
    const int lane  = tid & 31;
    const int plane = blockIdx.y;
    const int y0    = blockIdx.x * STRIP;
    const int wx0   = warp << 7;              // warp's first output col
    const int x0    = wx0 + (lane << 2);      // this thread's first output col

    const float* ip = in  + (size_t)plane * (W_IN  * H_IN);
    float*       op = out + (size_t)plane * (W_OUT * H_OUT);

    // Edge-load plan: lane0 -> col wx0-1, lane1 -> wx0+128, lane2 -> wx0+129.
    int  ecol;
    bool ep;
    if      (lane == 0) { ecol = wx0 - 1;   ep = (wx0 > 0); }
    else if (lane == 1) { ecol = wx0 + 128; ep = true; }             // <= 512 always
    else if (lane == 2) { ecol = wx0 + 129; ep = (wx0 + 129 < W_IN); }
    else                { ecol = wx0;       ep = false; }

    // Horizontal FIR for input row r (clamped; rm zeroes pad rows).
    auto hrow = [&](int r) -> float4 {
        const int   rc = min(max(r, 0), H_IN - 1);
        const float rm = ((unsigned)r < (unsigned)H_IN) ? 1.0f : 0.0f;
        const float* __restrict__ rp = ip + (size_t)rc * W_IN;

        float v0 = __ldg(rp + x0);
        float v1 = __ldg(rp + x0 + 1);
        float v2 = __ldg(rp + x0 + 2);
        float v3 = __ldg(rp + x0 + 3);
        float e  = ep ? __ldg(rp + ecol) : 0.0f;

        float e1  = __shfl_sync(FULL, e, 1);          // in[wx0+128]
        float e2  = __shfl_sync(FULL, e, 2);          // in[wx0+129]
        float t;
        t = __shfl_up_sync  (FULL, v3, 1); float xm1 = (lane ==  0) ? e  : t;  // in[x0-1]
        t = __shfl_down_sync(FULL, v0, 1); float xp4 = (lane == 31) ? e1 : t;  // in[x0+4]
        t = __shfl_down_sync(FULL, v1, 1); float xp5 = (lane == 31) ? e2 : t;  // in[x0+5]

        float4 h;
        h.x = (xm1 + 3.0f * (v0 + v1) + v2) * rm;
        h.y = (v0  + 3.0f * (v1 + v2) + v3) * rm;
        h.z = (v1  + 3.0f * (v2 + v3) + xp4) * rm;
        h.w = (v2  + 3.0f * (v3 + xp4) + xp5) * rm;
        return h;
    };

    float4 h[4];
    h[0] = hrow(y0 - 1);
    h[1] = hrow(y0);
    h[2] = hrow(y0 + 1);

    #pragma unroll 4
    for (int i = 0; i < STRIP; ++i) {
        float4 hd = hrow(y0 + 2 + i);
        h[(i + 3) & 3] = hd;
        float4 ha = h[ i      & 3];
        float4 hb = h[(i + 1) & 3];
        float4 hc = h[(i + 2) & 3];

        float4 o;
        o.x = (ha.x + hd.x + 3.0f * (hb.x + hc.x)) * 0.0625f;
        o.y = (ha.y + hd.y + 3.0f * (hb.y + hc.y)) * 0.0625f;
        o.z = (ha.z + hd.z + 3.0f * (hb.z + hc.z)) * 0.0625f;
        o.w = (ha.w + hd.w + 3.0f * (hb.w + hc.w)) * 0.0625f;

        __stcs(reinterpret_cast<float4*>(op + (size_t)(y0 + i) * W_OUT + x0), o);
    }
}

extern "C" void kernel_launch(void* const* d_in, const int* in_sizes, int n_in,
                              void* d_out, int out_size)
{
    const float* in  = (const float*)d_in[0];
    float*       out = (float*)d_out;
    // d_in[1] is the 4x4 FIR buffer: fixed normalized [1,3,3,1] outer product
    // * factor^2 == ([1,3,3,1] ⊗ [1,3,3,1]) / 16, folded into the constants.

    dim3 grid(H_OUT / STRIP, NPLANE);   // (8, 512)
    blur_shfl10_kernel<<<grid, 128>>>(in, out);
}

// round 9
// speedup vs baseline: 1.0260x; 1.0260x over previous
#include <cuda_runtime.h>

// Blur: depthwise 4x4 FIR (separable [1,3,3,1] ⊗ [1,3,3,1] / 16), pad (1,1).
// Input (4,128,513,513) f32 -> Output (4,128,512,512) f32.
//
// Round-9: identical to the R7 fence-free shuffle kernel (no smem, no sync,
// halo via shfl + 1 predicated edge load, 4-entry vertical register ring,
// STG.128 stores, 8 CTAs/SM so ptxas keeps its 60-reg schedule) with ONE
// change: STRIP 64 -> 32. Grid becomes 8192 blocks = 6.92 waves at 8 CTA/SM,
// shrinking the partial-wave tail from ~13% of runtime to ~1%.

#define W_IN   513
#define H_IN   513
#define W_OUT  512
#define H_OUT  512
#define STRIP  32
#define NPLANE 512      // 4*128
#define FULL   0xffffffffu

__global__ __launch_bounds__(128, 8)
void blur_shfl32_kernel(const float* __restrict__ in, float* __restrict__ out)
{
    const int tid   = threadIdx.x;
    const int warp  = tid >> 5;
    const int lane  = tid & 31;
    const int plane = blockIdx.y;
    const int y0    = blockIdx.x * STRIP;
    const int wx0   = warp << 7;              // warp's first output col
    const int x0    = wx0 + (lane << 2);      // this thread's first output col

    const float* ip = in  + (size_t)plane * (W_IN  * H_IN);
    float*       op = out + (size_t)plane * (W_OUT * H_OUT);

    // Edge-load plan: lane0 -> col wx0-1, lane1 -> wx0+128, lane2 -> wx0+129.
    int  ecol;
    bool ep;
    if      (lane == 0) { ecol = wx0 - 1;   ep = (wx0 > 0); }
    else if (lane == 1) { ecol = wx0 + 128; ep = true; }             // <= 512 always
    else if (lane == 2) { ecol = wx0 + 129; ep = (wx0 + 129 < W_IN); }
    else                { ecol = wx0;       ep = false; }

    // Horizontal FIR for input row r (clamped; rm zeroes pad rows).
    auto hrow = [&](int r) -> float4 {
        const int   rc = min(max(r, 0), H_IN - 1);
        const float rm = ((unsigned)r < (unsigned)H_IN) ? 1.0f : 0.0f;
        const float* __restrict__ rp = ip + (size_t)rc * W_IN;

        float v0 = __ldg(rp + x0);
        float v1 = __ldg(rp + x0 + 1);
        float v2 = __ldg(rp + x0 + 2);
        float v3 = __ldg(rp + x0 + 3);
        float e  = ep ? __ldg(rp + ecol) : 0.0f;

        float e1  = __shfl_sync(FULL, e, 1);          // in[wx0+128]
        float e2  = __shfl_sync(FULL, e, 2);          // in[wx0+129]
        float t;
        t = __shfl_up_sync  (FULL, v3, 1); float xm1 = (lane ==  0) ? e  : t;  // in[x0-1]
        t = __shfl_down_sync(FULL, v0, 1); float xp4 = (lane == 31) ? e1 : t;  // in[x0+4]
        t = __shfl_down_sync(FULL, v1, 1); float xp5 = (lane == 31) ? e2 : t;  // in[x0+5]

        float4 h;
        h.x = (xm1 + 3.0f * (v0 + v1) + v2) * rm;
        h.y = (v0  + 3.0f * (v1 + v2) + v3) * rm;
        h.z = (v1  + 3.0f * (v2 + v3) + xp4) * rm;
        h.w = (v2  + 3.0f * (v3 + xp4) + xp5) * rm;
        return h;
    };

    float4 h[4];
    h[0] = hrow(y0 - 1);
    h[1] = hrow(y0);
    h[2] = hrow(y0 + 1);

    #pragma unroll 4
    for (int i = 0; i < STRIP; ++i) {
        float4 hd = hrow(y0 + 2 + i);
        h[(i + 3) & 3] = hd;
        float4 ha = h[ i      & 3];
        float4 hb = h[(i + 1) & 3];
        float4 hc = h[(i + 2) & 3];

        float4 o;
        o.x = (ha.x + hd.x + 3.0f * (hb.x + hc.x)) * 0.0625f;
        o.y = (ha.y + hd.y + 3.0f * (hb.y + hc.y)) * 0.0625f;
        o.z = (ha.z + hd.z + 3.0f * (hb.z + hc.z)) * 0.0625f;
        o.w = (ha.w + hd.w + 3.0f * (hb.w + hc.w)) * 0.0625f;

        *reinterpret_cast<float4*>(op + (size_t)(y0 + i) * W_OUT + x0) = o;
    }
}

extern "C" void kernel_launch(void* const* d_in, const int* in_sizes, int n_in,
                              void* d_out, int out_size)
{
    const float* in  = (const float*)d_in[0];
    float*       out = (float*)d_out;
    // d_in[1] is the 4x4 FIR buffer: fixed normalized [1,3,3,1] outer product
    // * factor^2 == ([1,3,3,1] ⊗ [1,3,3,1]) / 16, folded into the constants.

    dim3 grid(H_OUT / STRIP, NPLANE);   // (16, 512)
    blur_shfl32_kernel<<<grid, 128>>>(in, out);
}